// round 10
// baseline (speedup 1.0000x reference)
#include <cuda_runtime.h>
#include <cuda_fp16.h>
#include <cstdint>
#include <cstddef>

#define Bz 1024
#define Tz 64
#define Dz 512
#define Hz 512
#define G4 2048
#define Kz 512

// ---------------- scratch (static __device__, allocation-free) ----------------
__device__ __align__(256) __half g_h2[2 * Bz * Hz];             // double-buffered fp16 h
__device__ __align__(256) __half g_wx[(size_t)Bz * Tz * Dz];    // 64 MB fp16 wx
__device__ __align__(256) __half g_wih[G4 * Dz];                // interleaved rows, fp16
__device__ __align__(256) __half g_whh[G4 * Hz];
__device__ __align__(256) float g_bias[G4];                     // interleaved cols
__device__ unsigned g_flag[128];                                // per-(bm,bn) producer flags

// ---------------- helpers ----------------
__device__ __forceinline__ uint32_t smem_u32(const void* p) {
    uint32_t a;
    asm("{ .reg .u64 t; cvta.to.shared.u64 t, %1; cvt.u32.u64 %0, t; }" : "=r"(a) : "l"(p));
    return a;
}
__device__ __forceinline__ unsigned ld_acq(const unsigned* p) {
    unsigned v;
    asm volatile("ld.acquire.gpu.global.u32 %0, [%1];" : "=r"(v) : "l"(p));
    return v;
}
__device__ __forceinline__ float frcp(float x) {
    float r;
    asm("rcp.approx.f32 %0, %1;" : "=f"(r) : "f"(x));
    return r;
}
__device__ __forceinline__ float sigm(float x) { return frcp(1.f + __expf(-x)); }
__device__ __forceinline__ float tanh_f(float x) { return fmaf(2.f, frcp(1.f + __expf(-2.f * x)), -1.f); }

#define LDSM4(r, addr)                                                      \
    asm volatile("ldmatrix.sync.aligned.m8n8.x4.shared.b16 {%0,%1,%2,%3}, [%4];" \
                 : "=r"((r)[0]), "=r"((r)[1]), "=r"((r)[2]), "=r"((r)[3])   \
                 : "r"(addr))

#define MMA(d, a, b0, b1)                                                   \
    asm volatile("mma.sync.aligned.m16n8k16.row.col.f32.f16.f16.f32 "       \
                 "{%0,%1,%2,%3}, {%4,%5,%6,%7}, {%8,%9}, {%0,%1,%2,%3};"    \
                 : "+f"((d)[0]), "+f"((d)[1]), "+f"((d)[2]), "+f"((d)[3])   \
                 : "r"((a)[0]), "r"((a)[1]), "r"((a)[2]), "r"((a)[3]),      \
                   "r"(b0), "r"(b1))

#define CP_ASYNC16(s, g) \
    asm volatile("cp.async.cg.shared.global [%0], [%1], 16;" :: "r"(s), "l"(g))
#define CP_COMMIT() asm volatile("cp.async.commit_group;" ::: "memory")
#define CP_WAIT(n)  asm volatile("cp.async.wait_group %0;" :: "n"(n) : "memory")

// ---- gemm_rec smem layout ----
#define BRP 1040                           // W_hh resident pitch (512 halves + 16B pad)
#define STG_OFF (128 * BRP)                // 133120
#define STG_SZ 16384                       // per stage: A (8KB swizzled) + B (8KB swizzled)
#define REC_SMEM (STG_OFF + 3 * STG_SZ)    // 182272

// ---------------- init ----------------
__global__ void init_kernel() {
    int i = blockIdx.x * blockDim.x + threadIdx.x;
    if (i < Bz * Hz) g_h2[i] = __float2half(0.f);   // buffer 0 = h(t=0)
    if (i < 128) g_flag[i] = 0u;
}

// ---------------- fused attn + wx ----------------
__global__ void __launch_bounds__(512)
attn_wx_kernel(const float* __restrict__ x, const float* __restrict__ w_attn,
               float* __restrict__ out_w) {
    int b = blockIdx.x;
    int d = threadIdx.x;
    __shared__ float wxs[Tz];
    __shared__ float red[Dz];
    if (d < Tz) wxs[d] = w_attn[2 * Hz + d];
    __syncthreads();
    const float* xb = x + (size_t)b * Tz * Dz + d;
    float acc = 0.f;
#pragma unroll 8
    for (int t = 0; t < Tz; t++) acc = fmaf(xb[(size_t)t * Dz], wxs[t], acc);
    red[d] = acc;
    __syncthreads();
    for (int s = 256; s > 0; s >>= 1) {
        if (d < s) red[d] = fmaxf(red[d], red[d + s]);
        __syncthreads();
    }
    float m = red[0];
    __syncthreads();
    float e = __expf(acc - m);
    red[d] = e;
    __syncthreads();
    for (int s = 256; s > 0; s >>= 1) {
        if (d < s) red[d] += red[d + s];
        __syncthreads();
    }
    float a = e / red[0];
    float* owb = out_w + (size_t)b * Tz * Dz + d;
    __half* wxb = g_wx + (size_t)b * Tz * Dz + d;
#pragma unroll 4
    for (int t = 0; t < Tz; t++) {
        float v = xb[(size_t)t * Dz] * a;
        owb[(size_t)t * Dz] = v;
        wxb[(size_t)t * Dz] = __float2half_rn(v);
    }
}

// ---------------- weight prep: interleave rows, fp16 ----------------
// nr for (gate g, unit u): nr = (u/8)*32 + g*8 + (u%8)
__global__ void prep_w_kernel(const float* __restrict__ wih, const float* __restrict__ whh,
                              const float* __restrict__ bih, const float* __restrict__ bhh) {
    int i = blockIdx.x * blockDim.x + threadIdx.x;
    if (i < G4 * Kz) {
        int row = i >> 9;
        int k = i & 511;
        int g = row >> 9;
        int u = row & 511;
        int nr = ((u >> 3) << 5) + (g << 3) + (u & 7);
        g_wih[nr * 512 + k] = __float2half_rn(wih[i]);
        g_whh[nr * 512 + k] = __float2half_rn(whh[i]);
        if (i < G4) {
            int gg = i >> 9, uu = i & 511;
            int nb = ((uu >> 3) << 5) + (gg << 3) + (uu & 7);
            g_bias[nb] = bih[i] + bhh[i];
        }
    }
}

// ---------------- persistent fused encoder: x-GEMM + h-GEMM + LSTM per step ----------------
__global__ void __launch_bounds__(256)
gemm_rec(float* __restrict__ out_enc) {
    extern __shared__ char smem[];
    const int tid = threadIdx.x;
    const int lane = tid & 31, wid = tid >> 5;
    const int wm = wid >> 2, wn = wid & 3;
    const int bn = blockIdx.x & 15, bm = blockIdx.x >> 4;
    const int swl = (lane >> 1) & 3;            // A-operand swizzle key
    const int swb = ((lane & 7) >> 1) & 3;      // B-operand swizzle key

    // ---- W_hh tile resident (128 gate-cols x 512 k) ----
    for (int i = tid; i < 8192; i += 256) {
        int row = i >> 6, c = i & 63;
        CP_ASYNC16(smem_u32(smem + row * BRP + c * 16),
                   g_whh + (size_t)(bn * 128 + row) * 512 + c * 8);
    }
    CP_COMMIT();
    CP_WAIT(0);
    __syncthreads();

    // per-thread bias (cols fixed for epilogue)
    const int cb = bn * 128 + wn * 32 + (lane & 3) * 2;
    const float2 bI = *(const float2*)(g_bias + cb + 0);
    const float2 bF = *(const float2*)(g_bias + cb + 8);
    const float2 bG = *(const float2*)(g_bias + cb + 16);
    const float2 bO = *(const float2*)(g_bias + cb + 24);

    const int U = (bn * 4 + wn) * 8 + (lane & 3) * 2;

    float c_reg[4][2][2];
#pragma unroll
    for (int mi = 0; mi < 4; mi++)
#pragma unroll
        for (int h = 0; h < 2; h++) { c_reg[mi][h][0] = 0.f; c_reg[mi][h][1] = 0.f; }

    for (int t = 0; t < Tz; t++) {
        // ================= x-part: acc = wx[:,t,:] @ W_ih'^T (no cross-step deps) =====
        auto prefX = [&](int j, int st) {
            int k0 = j * 32;
            char* sb = smem + STG_OFF + st * STG_SZ;
#pragma unroll
            for (int jj = 0; jj < 2; jj++) {
                int ci = tid * 2 + jj;
                int row = ci >> 2, c16 = ci & 3;
                int sw = (row >> 1) & 3;
                uint32_t soff = (uint32_t)(row * 64 + ((c16 ^ sw) << 4));
                CP_ASYNC16(smem_u32(sb + soff),
                           g_wx + ((size_t)(bm * 128 + row) * Tz + t) * Dz + k0 + c16 * 8);
                CP_ASYNC16(smem_u32(sb + 8192 + soff),
                           g_wih + (size_t)(bn * 128 + row) * Dz + k0 + c16 * 8);
            }
        };

        prefX(0, 0);
        CP_COMMIT();
        prefX(1, 1);
        CP_COMMIT();

        float acc[4][4][4];
#pragma unroll
        for (int a = 0; a < 4; a++)
#pragma unroll
            for (int b = 0; b < 4; b++)
#pragma unroll
                for (int c = 0; c < 4; c++) acc[a][b][c] = 0.f;

        int stage = 0;
        for (int j = 0; j < 16; j++) {
            if (j < 15) { CP_WAIT(1); } else { CP_WAIT(0); }
            __syncthreads();
            if (j + 2 < 16) {
                int ns = stage + 2;
                if (ns >= 3) ns -= 3;
                prefX(j + 2, ns);
                CP_COMMIT();
            }
            char* sa = smem + STG_OFF + stage * STG_SZ;
#pragma unroll
            for (int kk = 0; kk < 2; kk++) {
                uint32_t av[4][4], bq[2][4];
#pragma unroll
                for (int mi = 0; mi < 4; mi++) {
                    int row = wm * 64 + (lane & 15) + mi * 16;
                    int c16 = (lane >> 4) + kk * 2;
                    LDSM4(av[mi], smem_u32(sa + row * 64 + ((c16 ^ swl) << 4)));
                }
#pragma unroll
                for (int p = 0; p < 2; p++) {
                    int row = wn * 32 + (lane >> 4) * 8 + (lane & 7) + p * 16;
                    int c16 = kk * 2 + ((lane >> 3) & 1);
                    LDSM4(bq[p], smem_u32(sa + 8192 + row * 64 + ((c16 ^ swb) << 4)));
                }
#pragma unroll
                for (int mi = 0; mi < 4; mi++)
#pragma unroll
                    for (int ni = 0; ni < 4; ni++)
                        MMA(acc[mi][ni], av[mi], bq[ni >> 1][(ni & 1) * 2], bq[ni >> 1][(ni & 1) * 2 + 1]);
            }
            if (++stage == 3) stage = 0;
        }
        __syncthreads();   // protect stage buffers before h-part overwrites

        // ================= wait for h(t) producers of this bm group =================
        if (t) {
            if (tid < 16) {
                while (ld_acq(&g_flag[bm * 16 + tid]) < (unsigned)t) { }
            }
            __syncthreads();
        }

        // ================= h-part: acc += h(t) @ W_hh'^T (W_hh resident) ============
        const __half* A = g_h2 + (size_t)(t & 1) * Bz * Hz + (size_t)bm * 128 * Hz;
        auto prefA = [&](int c, int st) {
            int k0 = c * 32;
            char* sb = smem + STG_OFF + st * STG_SZ;
#pragma unroll
            for (int jj = 0; jj < 2; jj++) {
                int ci = tid * 2 + jj;
                int row = ci >> 2, c16 = ci & 3;
                int sw = (row >> 1) & 3;
                CP_ASYNC16(smem_u32(sb + row * 64 + ((c16 ^ sw) << 4)),
                           A + (size_t)row * Hz + k0 + c16 * 8);
            }
        };

        prefA(bn, 0);
        CP_COMMIT();
        prefA((bn + 1) & 15, 1);
        CP_COMMIT();

        stage = 0;
        for (int j = 0; j < 16; j++) {
            if (j < 15) { CP_WAIT(1); } else { CP_WAIT(0); }
            __syncthreads();
            if (j + 2 < 16) {
                int ns = stage + 2;
                if (ns >= 3) ns -= 3;
                prefA((bn + j + 2) & 15, ns);
                CP_COMMIT();
            }
            int c = (bn + j) & 15;
            char* sa = smem + STG_OFF + stage * STG_SZ;
#pragma unroll
            for (int kk = 0; kk < 2; kk++) {
                uint32_t av[4][4], bq[2][4];
#pragma unroll
                for (int mi = 0; mi < 4; mi++) {
                    int row = wm * 64 + (lane & 15) + mi * 16;
                    int c16 = (lane >> 4) + kk * 2;
                    LDSM4(av[mi], smem_u32(sa + row * 64 + ((c16 ^ swl) << 4)));
                }
                uint32_t b_off = (uint32_t)((wn * 32 + (lane >> 4) * 8 + (lane & 7)) * BRP +
                                            c * 64 + kk * 32 + ((lane >> 3) & 1) * 16);
#pragma unroll
                for (int p = 0; p < 2; p++)
                    LDSM4(bq[p], smem_u32(smem + b_off + p * 16 * BRP));
#pragma unroll
                for (int mi = 0; mi < 4; mi++)
#pragma unroll
                    for (int ni = 0; ni < 4; ni++)
                        MMA(acc[mi][ni], av[mi], bq[ni >> 1][(ni & 1) * 2], bq[ni >> 1][(ni & 1) * 2 + 1]);
            }
            if (++stage == 3) stage = 0;
        }

        // ================= fused LSTM epilogue (gates in registers) =================
        __half* hw = g_h2 + (size_t)((t + 1) & 1) * Bz * Hz;
#pragma unroll
        for (int mi = 0; mi < 4; mi++) {
#pragma unroll
            for (int half = 0; half < 2; half++) {
                int mloc = wm * 64 + mi * 16 + half * 8 + (lane >> 2);
                int m = bm * 128 + mloc;
                int j0 = half * 2;
                float gi0 = acc[mi][0][j0] + bI.x, gi1 = acc[mi][0][j0 + 1] + bI.y;
                float gf0 = acc[mi][1][j0] + bF.x, gf1 = acc[mi][1][j0 + 1] + bF.y;
                float gg0 = acc[mi][2][j0] + bG.x, gg1 = acc[mi][2][j0 + 1] + bG.y;
                float go0 = acc[mi][3][j0] + bO.x, go1 = acc[mi][3][j0 + 1] + bO.y;
                float c20 = sigm(gf0) * c_reg[mi][half][0] + sigm(gi0) * tanh_f(gg0);
                float c21 = sigm(gf1) * c_reg[mi][half][1] + sigm(gi1) * tanh_f(gg1);
                c_reg[mi][half][0] = c20;
                c_reg[mi][half][1] = c21;
                float h20 = sigm(go0) * tanh_f(c20);
                float h21 = sigm(go1) * tanh_f(c21);
                *(float2*)(out_enc + ((size_t)m * Tz + t) * Hz + U) = make_float2(h20, h21);
                *(__half2*)(hw + (size_t)m * Hz + U) =
                    __half2(__float2half_rn(h20), __float2half_rn(h21));
            }
        }

        // ---- publish h(t+1) ----
        __threadfence();
        __syncthreads();
        if (tid == 0) atomicAdd(&g_flag[bm * 16 + bn], 1u);
    }
}

// ---------------- launch ----------------
extern "C" void kernel_launch(void* const* d_in, const int* in_sizes, int n_in,
                              void* d_out, int out_size) {
    const float* x      = (const float*)d_in[0];
    const float* w_ih   = (const float*)d_in[1];
    const float* w_hh   = (const float*)d_in[2];
    const float* b_ih   = (const float*)d_in[3];
    const float* b_hh   = (const float*)d_in[4];
    const float* w_attn = (const float*)d_in[5];
    (void)in_sizes; (void)n_in; (void)out_size;

    float* out_w   = (float*)d_out;
    float* out_enc = out_w + (size_t)Bz * Tz * Dz;

    static int attr_done = 0;
    if (!attr_done) {
        cudaFuncSetAttribute(gemm_rec, cudaFuncAttributeMaxDynamicSharedMemorySize, REC_SMEM);
        attr_done = 1;
    }

    init_kernel<<<(Bz * Hz + 255) / 256, 256>>>();
    attn_wx_kernel<<<Bz, Dz>>>(x, w_attn, out_w);
    prep_w_kernel<<<(G4 * Kz + 255) / 256, 256>>>(w_ih, w_hh, b_ih, b_hh);

    // persistent fused encoder: x-GEMM + recurrence + LSTM, all 64 steps
    gemm_rec<<<128, 256, REC_SMEM>>>(out_enc);
}